// round 2
// baseline (speedup 1.0000x reference)
#include <cuda_runtime.h>
#include <math.h>

#define D_DEPTH 128
#define BEV 128
#define CELL (BEV*BEV)
#define RES_F 0.025f
#define X_MIN_F (-1.6f)
#define Z_MAX_F 3.3f
#define MIN_DEPTH_F (0.1f + 0.0125f)   /* Z_MIN + RES/2 */
#define LOG_U3 (-1.0986f)
#define EPSC 1e-7f

// Scratch table: log class-probs, up to 4 batches. (B,3,128,128)
__device__ float g_logcp[4 * 3 * CELL];

// ---------------------------------------------------------------------------
// Kernel 1: bev_logits (B,2,128,128) -> log class probs (B,3,128,128)
// ---------------------------------------------------------------------------
__global__ void bev_table_kernel(const float* __restrict__ bev, int B) {
    int idx = blockIdx.x * blockDim.x + threadIdx.x;
    if (idx >= B * CELL) return;
    int b = idx / CELL, zx = idx - b * CELL;
    float l0 = bev[(b * 2 + 0) * CELL + zx];
    float l1 = bev[(b * 2 + 1) * CELL + zx];
    float p0 = 1.0f / (1.0f + __expf(-l0));
    float p1 = 1.0f / (1.0f + __expf(-l1));
    p0 = fminf(fmaxf(p0, EPSC), 1.0f - EPSC);
    p1 = fminf(fmaxf(p1, EPSC), 1.0f - EPSC);
    g_logcp[(b * 3 + 0) * CELL + zx] = __logf(1.0f - p1);
    g_logcp[(b * 3 + 1) * CELL + zx] = __logf(p1 * p0);
    g_logcp[(b * 3 + 2) * CELL + zx] = __logf(p1 * (1.0f - p0));
}

// ---------------------------------------------------------------------------
// Kernel 2: main decode. Block = 32 contiguous pixels (same row) x 128 depths.
// blockDim = 256 (32 lanes x 8 warps). Phase 3 stages each pixel's 384
// output floats in shared, then emits fully-coalesced STG.128 stores.
// ---------------------------------------------------------------------------
__global__ __launch_bounds__(256) void decode_kernel(
    const float* __restrict__ dl,    // (B, D, H, W)
    const float* __restrict__ invK,  // (B, 4, 4)
    float* __restrict__ out,         // (B, H, W, D, 3)
    int H, int W)
{
    __shared__ float sm[D_DEPTH][33];   // logit tile, pitch 33: d-strided reads conflict-free
    __shared__ float red[8][32];
    __shared__ float shiftv[32];        // per-pixel: first max, then -(max+lse)
    __shared__ float cam0s[32], cam1s[32], cam2s[32];
    __shared__ float stage[8][D_DEPTH * 3];  // per-warp output staging (1536 B each)

    const int tid = threadIdx.x;
    const int tx = tid & 31;            // lane
    const int ty = tid >> 5;            // warp id
    const int tilesPerRow = W >> 5;

    int bid = blockIdx.x;
    int w0 = (bid % tilesPerRow) << 5;
    int h  = (bid / tilesPerRow) % H;
    int b  =  bid / (tilesPerRow * H);

    const size_t HW = (size_t)H * W;
    const float* base = dl + ((size_t)b * D_DEPTH) * HW + (size_t)h * W + w0;

    // Phase 1: coalesced load of 128 x 32 logit tile into shared
    #pragma unroll
    for (int j = 0; j < 16; j++) {
        int d = ty + j * 8;
        sm[d][tx] = base[(size_t)d * HW + tx];
    }
    if (ty == 0) {
        const float* k = invK + (size_t)b * 16;
        float x = (float)(w0 + tx), y = (float)h;
        cam0s[tx] = k[0] * x + k[1] * y + k[2];
        cam1s[tx] = k[4] * x + k[5] * y + k[6];
        cam2s[tx] = k[8] * x + k[9] * y + k[10];
    }
    __syncthreads();

    // Phase 2a: per-pixel max over D
    float m = -INFINITY;
    #pragma unroll
    for (int j = 0; j < 16; j++) m = fmaxf(m, sm[ty + j * 8][tx]);
    red[ty][tx] = m;
    __syncthreads();
    if (ty == 0) {
        float mm = red[0][tx];
        #pragma unroll
        for (int r = 1; r < 8; r++) mm = fmaxf(mm, red[r][tx]);
        shiftv[tx] = mm;
    }
    __syncthreads();
    float mpx = shiftv[tx];

    // Phase 2b: per-pixel sum(exp(x-max))
    float s = 0.0f;
    #pragma unroll
    for (int j = 0; j < 16; j++) s += __expf(sm[ty + j * 8][tx] - mpx);
    red[ty][tx] = s;
    __syncthreads();
    if (ty == 0) {
        float ss = 0.0f;
        #pragma unroll
        for (int r = 0; r < 8; r++) ss += red[r][tx];
        shiftv[tx] = -mpx - __logf(ss);   // log_softmax shift
    }
    __syncthreads();

    // Phase 3: each warp owns 4 pixels; per pixel compute all 128 depths,
    // stage 384 floats in shared (stride-3 writes, conflict-free), then
    // write out as 3 x STG.128 per pixel (1 wavefront / 128B, ideal).
    float* outp = out + (((size_t)b * H + h) * W + w0) * (size_t)(D_DEPTH * 3);
    const float* lcp = &g_logcp[(size_t)(b * 3) * CELL];

    #pragma unroll
    for (int i = 0; i < 4; i++) {
        const int px = (ty << 2) + i;
        const float ca0 = cam0s[px], ca1 = cam1s[px], ca2 = cam2s[px];
        const float sh = shiftv[px];

        #pragma unroll
        for (int j = 0; j < 4; j++) {
            int d = tx + (j << 5);
            float dlp  = sm[d][px] + sh;
            float dval = MIN_DEPTH_F + (float)d * RES_F;
            float X =  dval * ca0;
            float Y = -dval * ca1;
            float Z = -dval * ca2;

            int vx = (int)((X - X_MIN_F) / RES_F);   // trunc == astype(int32)
            int vy = (int)(Y / RES_F);
            int vz = (int)((Z + Z_MAX_F) / RES_F);

            bool valid = (vx >= 0) & (vx < BEV) & (vz >= 0) & (vz < BEV) & (vy <= 0);

            float v0, v1, v2;
            if (valid) {
                int o = vz * BEV + vx;
                v0 = lcp[o];
                v1 = lcp[o + CELL];
                v2 = lcp[o + 2 * CELL];
            } else {
                v0 = v1 = v2 = LOG_U3;
            }
            stage[ty][d * 3 + 0] = v0 + dlp;
            stage[ty][d * 3 + 1] = v1 + dlp;
            stage[ty][d * 3 + 2] = v2 + dlp;
        }
        __syncwarp();

        const float4* sg = (const float4*)stage[ty];
        float4* og = (float4*)(outp + (size_t)px * (D_DEPTH * 3));
        #pragma unroll
        for (int q = 0; q < 3; q++) {
            float4 v = sg[tx + (q << 5)];
            __stcs(&og[tx + (q << 5)], v);   // streaming: output never re-read
        }
        __syncwarp();
    }
}

// ---------------------------------------------------------------------------
extern "C" void kernel_launch(void* const* d_in, const int* in_sizes, int n_in,
                              void* d_out, int out_size) {
    const float* depth = (const float*)d_in[0];   // depth_logits (B,128,H,W)
    const float* bev   = (const float*)d_in[1];   // bev_logits   (B,2,128,128)
    const float* invK  = (const float*)d_in[2];   // inv_K        (B,4,4)
    float* out = (float*)d_out;

    int B = in_sizes[2] / 16;
    long long HW = (long long)in_sizes[0] / ((long long)B * D_DEPTH);
    int W = 1;
    while ((long long)W * W < HW) W <<= 1;        // square, power-of-two dims
    int H = (int)(HW / W);

    bev_table_kernel<<<(B * CELL + 255) / 256, 256>>>(bev, B);
    decode_kernel<<<B * H * (W / 32), 256>>>(depth, invK, out, H, W);
}

// round 3
// speedup vs baseline: 1.1593x; 1.1593x over previous
#include <cuda_runtime.h>
#include <math.h>

#define D_DEPTH 128
#define BEV 128
#define CELL (BEV*BEV)
#define RES_F 0.025f
#define X_MIN_F (-1.6f)
#define Z_MAX_F 3.3f
#define MIN_DEPTH_F (0.1f + 0.0125f)   /* Z_MIN + RES/2 */
#define LOG_U3 (-1.0986f)
#define EPSC 1e-7f

// Scratch table: log class-probs, up to 4 batches. (B,3,128,128)
__device__ float g_logcp[4 * 3 * CELL];

// ---------------------------------------------------------------------------
// Kernel 1: bev_logits (B,2,128,128) -> log class probs (B,3,128,128)
// ---------------------------------------------------------------------------
__global__ void bev_table_kernel(const float* __restrict__ bev, int B) {
    int idx = blockIdx.x * blockDim.x + threadIdx.x;
    if (idx >= B * CELL) return;
    int b = idx / CELL, zx = idx - b * CELL;
    float l0 = bev[(b * 2 + 0) * CELL + zx];
    float l1 = bev[(b * 2 + 1) * CELL + zx];
    float p0 = 1.0f / (1.0f + __expf(-l0));
    float p1 = 1.0f / (1.0f + __expf(-l1));
    p0 = fminf(fmaxf(p0, EPSC), 1.0f - EPSC);
    p1 = fminf(fmaxf(p1, EPSC), 1.0f - EPSC);
    g_logcp[(b * 3 + 0) * CELL + zx] = __logf(1.0f - p1);
    g_logcp[(b * 3 + 1) * CELL + zx] = __logf(p1 * p0);
    g_logcp[(b * 3 + 2) * CELL + zx] = __logf(p1 * (1.0f - p0));
}

// ---------------------------------------------------------------------------
// Voxel evaluation for one (pixel, depth): returns dlp-shifted validity + base
// ---------------------------------------------------------------------------
struct DEval { float dlp; int obase; int valid; };

__device__ __forceinline__ DEval eval_depth(
    float logit, float sh, float ca0, float ca1, float ca2, int d)
{
    DEval r;
    r.dlp = logit + sh;
    float dval = MIN_DEPTH_F + (float)d * RES_F;
    float X =  dval * ca0;
    float Y = -dval * ca1;
    float Z = -dval * ca2;
    int vx = (int)((X - X_MIN_F) / RES_F);   // trunc == astype(int32)
    int vy = (int)(Y / RES_F);
    int vz = (int)((Z + Z_MAX_F) / RES_F);
    r.valid = (vx >= 0) & (vx < BEV) & (vz >= 0) & (vz < BEV) & (vy <= 0);
    r.obase = vz * BEV + vx;
    return r;
}

// ---------------------------------------------------------------------------
// Kernel 2: main decode. Block = 32 contiguous pixels (same row) x 128 depths.
// blockDim = 256 (32 lanes x 8 warps). Phase 3: each lane produces one
// float4 of FINAL output layout directly -> pure STG.128, no staging.
// ---------------------------------------------------------------------------
__global__ __launch_bounds__(256) void decode_kernel(
    const float* __restrict__ dl,    // (B, D, H, W)
    const float* __restrict__ invK,  // (B, 4, 4)
    float* __restrict__ out,         // (B, H, W, D, 3)
    int H, int W)
{
    __shared__ float sm[D_DEPTH][33];   // logit tile, pitch 33
    __shared__ float red[8][32];
    __shared__ float shiftv[32];        // per-pixel: first max, then -(max+lse)
    __shared__ float cam0s[32], cam1s[32], cam2s[32];

    const int tid = threadIdx.x;
    const int tx = tid & 31;            // lane
    const int ty = tid >> 5;            // warp id
    const int tilesPerRow = W >> 5;

    int bid = blockIdx.x;
    int w0 = (bid % tilesPerRow) << 5;
    int h  = (bid / tilesPerRow) % H;
    int b  =  bid / (tilesPerRow * H);

    const size_t HW = (size_t)H * W;
    const float* base = dl + ((size_t)b * D_DEPTH) * HW + (size_t)h * W + w0;

    // Phase 1: coalesced load of 128 x 32 logit tile into shared
    #pragma unroll
    for (int j = 0; j < 16; j++) {
        int d = ty + j * 8;
        sm[d][tx] = base[(size_t)d * HW + tx];
    }
    if (ty == 0) {
        const float* k = invK + (size_t)b * 16;
        float x = (float)(w0 + tx), y = (float)h;
        cam0s[tx] = k[0] * x + k[1] * y + k[2];
        cam1s[tx] = k[4] * x + k[5] * y + k[6];
        cam2s[tx] = k[8] * x + k[9] * y + k[10];
    }
    __syncthreads();

    // Phase 2a: per-pixel max over D
    float m = -INFINITY;
    #pragma unroll
    for (int j = 0; j < 16; j++) m = fmaxf(m, sm[ty + j * 8][tx]);
    red[ty][tx] = m;
    __syncthreads();
    if (ty == 0) {
        float mm = red[0][tx];
        #pragma unroll
        for (int r = 1; r < 8; r++) mm = fmaxf(mm, red[r][tx]);
        shiftv[tx] = mm;
    }
    __syncthreads();
    float mpx = shiftv[tx];

    // Phase 2b: per-pixel sum(exp(x-max))
    float s = 0.0f;
    #pragma unroll
    for (int j = 0; j < 16; j++) s += __expf(sm[ty + j * 8][tx] - mpx);
    red[ty][tx] = s;
    __syncthreads();
    if (ty == 0) {
        float ss = 0.0f;
        #pragma unroll
        for (int r = 0; r < 8; r++) ss += red[r][tx];
        shiftv[tx] = -mpx - __logf(ss);   // log_softmax shift
    }
    __syncthreads();

    // Phase 3: warp owns 4 pixels. Per pixel: 3 iterations; lane L produces
    // output elements e = q*128 + 4L .. +3 (d=e/3, c=e%3) as one float4.
    float* outp = out + (((size_t)b * H + h) * W + w0) * (size_t)(D_DEPTH * 3);
    const float* lcp = &g_logcp[(size_t)(b * 3) * CELL];

    #pragma unroll
    for (int i = 0; i < 4; i++) {
        const int px = (ty << 2) + i;
        const float ca0 = cam0s[px], ca1 = cam1s[px], ca2 = cam2s[px];
        const float sh = shiftv[px];
        float4* og = (float4*)(outp + (size_t)px * (D_DEPTH * 3));

        #pragma unroll
        for (int q = 0; q < 3; q++) {
            int e0 = (q << 7) + (tx << 2);
            int da = e0 / 3;                 // lane's first depth bin
            int r0 = e0 - 3 * da;            // e0 mod 3
            int db = da + 1;                 // da<=126 so db<=127 always

            DEval A = eval_depth(sm[da][px], sh, ca0, ca1, ca2, da);
            DEval B = eval_depth(sm[db][px], sh, ca0, ca1, ca2, db);

            float v[4];
            #pragma unroll
            for (int k = 0; k < 3 + 1; k++) {
                int c = r0 + k;
                int useB = (c >= 3);
                if (useB) c -= 3;
                float dlp  = useB ? B.dlp : A.dlp;
                int   ok   = useB ? B.valid : A.valid;
                int   o    = (useB ? B.obase : A.obase) + c * CELL;
                float t = LOG_U3;
                if (ok) t = __ldg(&lcp[o]);  // predicated gather
                v[k] = t + dlp;
            }
            float4 pk = make_float4(v[0], v[1], v[2], v[3]);
            __stcs(&og[(q << 5) + tx], pk);  // fully coalesced STG.128
        }
    }
}

// ---------------------------------------------------------------------------
extern "C" void kernel_launch(void* const* d_in, const int* in_sizes, int n_in,
                              void* d_out, int out_size) {
    const float* depth = (const float*)d_in[0];   // depth_logits (B,128,H,W)
    const float* bev   = (const float*)d_in[1];   // bev_logits   (B,2,128,128)
    const float* invK  = (const float*)d_in[2];   // inv_K        (B,4,4)
    float* out = (float*)d_out;

    int B = in_sizes[2] / 16;
    long long HW = (long long)in_sizes[0] / ((long long)B * D_DEPTH);
    int W = 1;
    while ((long long)W * W < HW) W <<= 1;        // square, power-of-two dims
    int H = (int)(HW / W);

    bev_table_kernel<<<(B * CELL + 255) / 256, 256>>>(bev, B);
    decode_kernel<<<B * H * (W / 32), 256>>>(depth, invK, out, H, W);
}

// round 4
// speedup vs baseline: 1.3069x; 1.1274x over previous
#include <cuda_runtime.h>
#include <math.h>

#define D_DEPTH 128
#define BEV 128
#define CELL (BEV*BEV)
#define RES_F 0.025f
#define X_MIN_F (-1.6f)
#define Z_MAX_F 3.3f
#define MIN_DEPTH_F (0.1f + 0.0125f)   /* Z_MIN + RES/2 */
#define LOG_U3 (-1.0986f)
#define EPSC 1e-7f

// Interleaved class table: per BEV cell a float4 {logc0, logc1, logc2, 0}.
// Up to 4 batches. 4 * 16384 * 16B = 1 MB, L2-resident.
__device__ float4 g_logcp4[4 * CELL];

// ---------------------------------------------------------------------------
// Kernel 1: bev_logits (B,2,128,128) -> interleaved log class probs
// ---------------------------------------------------------------------------
__global__ void bev_table_kernel(const float* __restrict__ bev, int B) {
    int idx = blockIdx.x * blockDim.x + threadIdx.x;
    if (idx >= B * CELL) return;
    int b = idx / CELL, zx = idx - b * CELL;
    float l0 = bev[(b * 2 + 0) * CELL + zx];
    float l1 = bev[(b * 2 + 1) * CELL + zx];
    float p0 = 1.0f / (1.0f + __expf(-l0));
    float p1 = 1.0f / (1.0f + __expf(-l1));
    p0 = fminf(fmaxf(p0, EPSC), 1.0f - EPSC);
    p1 = fminf(fmaxf(p1, EPSC), 1.0f - EPSC);
    g_logcp4[b * CELL + zx] = make_float4(
        __logf(1.0f - p1), __logf(p1 * p0), __logf(p1 * (1.0f - p0)), 0.0f);
}

// ---------------------------------------------------------------------------
// Per-(pixel,depth) evaluation
// ---------------------------------------------------------------------------
struct DEval { float dlp; int obase; int valid; };

__device__ __forceinline__ DEval eval_depth(
    float logit, float sh, float ca0, float ca1, float ca2, int d)
{
    DEval r;
    r.dlp = logit + sh;
    float dval = MIN_DEPTH_F + (float)d * RES_F;
    float X =  dval * ca0;
    float Y = -dval * ca1;
    float Z = -dval * ca2;
    int vx = (int)((X - X_MIN_F) / RES_F);   // trunc == astype(int32)
    int vz = (int)((Z + Z_MAX_F) / RES_F);
    float qy = Y / RES_F;                    // trunc(qy) <= 0  <=>  qy < 1.0
    r.valid = (vx >= 0) & (vx < BEV) & (vz >= 0) & (vz < BEV) & (qy < 1.0f);
    r.obase = vz * BEV + vx;
    return r;
}

// ---------------------------------------------------------------------------
// Kernel 2: main decode. Block = 32 contiguous pixels x 128 depths.
// blockDim = 256 (32 lanes x 8 warps). Phase 3: each lane emits one float4
// of FINAL output per q (pure coalesced STG.128), gathers via 2x LDG.128.
// ---------------------------------------------------------------------------
__global__ __launch_bounds__(256, 6) void decode_kernel(
    const float* __restrict__ dl,    // (B, D, H, W)
    const float* __restrict__ invK,  // (B, 4, 4)
    float* __restrict__ out,         // (B, H, W, D, 3)
    int H, int W)
{
    __shared__ float sm[D_DEPTH][33];   // logit tile, pitch 33
    __shared__ float red[8][32];
    __shared__ float shiftv[32];
    __shared__ float cam0s[32], cam1s[32], cam2s[32];

    const int tid = threadIdx.x;
    const int tx = tid & 31;
    const int ty = tid >> 5;
    const int tilesPerRow = W >> 5;

    int bid = blockIdx.x;
    int w0 = (bid % tilesPerRow) << 5;
    int h  = (bid / tilesPerRow) % H;
    int b  =  bid / (tilesPerRow * H);

    const size_t HW = (size_t)H * W;
    const float* base = dl + ((size_t)b * D_DEPTH) * HW + (size_t)h * W + w0;

    // Phase 1: coalesced load of 128 x 32 logit tile into shared
    #pragma unroll
    for (int j = 0; j < 16; j++) {
        int d = ty + j * 8;
        sm[d][tx] = base[(size_t)d * HW + tx];
    }
    if (ty == 0) {
        const float* k = invK + (size_t)b * 16;
        float x = (float)(w0 + tx), y = (float)h;
        cam0s[tx] = k[0] * x + k[1] * y + k[2];
        cam1s[tx] = k[4] * x + k[5] * y + k[6];
        cam2s[tx] = k[8] * x + k[9] * y + k[10];
    }
    __syncthreads();

    // Phase 2a: per-pixel max over D
    float m = -INFINITY;
    #pragma unroll
    for (int j = 0; j < 16; j++) m = fmaxf(m, sm[ty + j * 8][tx]);
    red[ty][tx] = m;
    __syncthreads();
    if (ty == 0) {
        float mm = red[0][tx];
        #pragma unroll
        for (int r = 1; r < 8; r++) mm = fmaxf(mm, red[r][tx]);
        shiftv[tx] = mm;
    }
    __syncthreads();
    float mpx = shiftv[tx];

    // Phase 2b: per-pixel sum(exp(x-max))
    float s = 0.0f;
    #pragma unroll
    for (int j = 0; j < 16; j++) s += __expf(sm[ty + j * 8][tx] - mpx);
    red[ty][tx] = s;
    __syncthreads();
    if (ty == 0) {
        float ss = 0.0f;
        #pragma unroll
        for (int r = 0; r < 8; r++) ss += red[r][tx];
        shiftv[tx] = -mpx - __logf(ss);   // log_softmax shift
    }
    __syncthreads();

    // Phase 3
    float* outp = out + (((size_t)b * H + h) * W + w0) * (size_t)(D_DEPTH * 3);
    const float4* t4 = &g_logcp4[(size_t)b * CELL];

    #pragma unroll
    for (int i = 0; i < 4; i++) {
        const int px = (ty << 2) + i;
        const float ca0 = cam0s[px], ca1 = cam1s[px], ca2 = cam2s[px];
        const float sh = shiftv[px];
        float4* og = (float4*)(outp + (size_t)px * (D_DEPTH * 3));

        #pragma unroll
        for (int q = 0; q < 3; q++) {
            int e0 = (q << 7) + (tx << 2);
            int da = e0 / 3;                 // lane's first depth bin
            int r0 = e0 - 3 * da;
            int db = da + 1;                 // da <= 126 always

            DEval A = eval_depth(sm[da][px], sh, ca0, ca1, ca2, da);
            DEval B = eval_depth(sm[db][px], sh, ca0, ca1, ca2, db);

            float4 fa = make_float4(LOG_U3, LOG_U3, LOG_U3, 0.0f);
            if (A.valid) fa = __ldg(&t4[A.obase]);
            float4 fb = make_float4(LOG_U3, LOG_U3, LOG_U3, 0.0f);
            if (B.valid) fb = __ldg(&t4[B.obase]);

            fa.x += A.dlp; fa.y += A.dlp; fa.z += A.dlp;
            fb.x += B.dlp; fb.y += B.dlp; fb.z += B.dlp;

            // element k has class c = r0+k; c<3 -> fa[c], else fb[c-3]
            float v0 = (r0 == 0) ? fa.x : ((r0 == 1) ? fa.y : fa.z);
            float v1 = (r0 == 0) ? fa.y : ((r0 == 1) ? fa.z : fb.x);
            float v2 = (r0 == 0) ? fa.z : ((r0 == 1) ? fb.x : fb.y);
            float v3 = (r0 == 0) ? fb.x : ((r0 == 1) ? fb.y : fb.z);

            __stcs(&og[(q << 5) + tx], make_float4(v0, v1, v2, v3));
        }
    }
}

// ---------------------------------------------------------------------------
extern "C" void kernel_launch(void* const* d_in, const int* in_sizes, int n_in,
                              void* d_out, int out_size) {
    const float* depth = (const float*)d_in[0];   // depth_logits (B,128,H,W)
    const float* bev   = (const float*)d_in[1];   // bev_logits   (B,2,128,128)
    const float* invK  = (const float*)d_in[2];   // inv_K        (B,4,4)
    float* out = (float*)d_out;

    int B = in_sizes[2] / 16;
    long long HW = (long long)in_sizes[0] / ((long long)B * D_DEPTH);
    int W = 1;
    while ((long long)W * W < HW) W <<= 1;        // square, power-of-two dims
    int H = (int)(HW / W);

    bev_table_kernel<<<(B * CELL + 255) / 256, 256>>>(bev, B);
    decode_kernel<<<B * H * (W / 32), 256>>>(depth, invK, out, H, W);
}

// round 5
// speedup vs baseline: 1.3852x; 1.0599x over previous
#include <cuda_runtime.h>
#include <math.h>

#define D_DEPTH 128
#define BEV 128
#define CELL (BEV*BEV)
#define RES_F 0.025f
#define X_MIN_F (-1.6f)
#define Z_MAX_F 3.3f
#define MIN_DEPTH_F (0.1f + 0.0125f)   /* Z_MIN + RES/2 */
#define LOG_U3 (-1.0986f)
#define EPSC 1e-7f

#define SM_PITCH 129      /* odd: conflict-free scalar access both directions */
#define ST_PITCH 100      /* = 4 mod 32 -> conflict-free (min-phase) 128-bit smem ops */

// Interleaved class table: per BEV cell a float4 {logc0, logc1, logc2, 0}.
__device__ float4 g_logcp4[4 * CELL];

// ---------------------------------------------------------------------------
// Kernel 1: bev_logits (B,2,128,128) -> interleaved log class probs
// ---------------------------------------------------------------------------
__global__ void bev_table_kernel(const float* __restrict__ bev, int B) {
    int idx = blockIdx.x * blockDim.x + threadIdx.x;
    if (idx >= B * CELL) return;
    int b = idx / CELL, zx = idx - b * CELL;
    float l0 = bev[(b * 2 + 0) * CELL + zx];
    float l1 = bev[(b * 2 + 1) * CELL + zx];
    float p0 = 1.0f / (1.0f + __expf(-l0));
    float p1 = 1.0f / (1.0f + __expf(-l1));
    p0 = fminf(fmaxf(p0, EPSC), 1.0f - EPSC);
    p1 = fminf(fmaxf(p1, EPSC), 1.0f - EPSC);
    g_logcp4[b * CELL + zx] = make_float4(
        __logf(1.0f - p1), __logf(p1 * p0), __logf(p1 * (1.0f - p0)), 0.0f);
}

// ---------------------------------------------------------------------------
// Kernel 2: block = 32 pixels x 128 depths, 256 threads (32 lanes x 8 warps).
// Phase 3a: lane=pixel -> warp-uniform vz, gather touches 2-3 lines/instr.
// Phase 3b: staged transpose -> wavefront-exact coalesced STG.128.
// ---------------------------------------------------------------------------
__global__ __launch_bounds__(256, 6) void decode_kernel(
    const float* __restrict__ dl,    // (B, D, H, W)
    const float* __restrict__ invK,  // (B, 4, 4)
    float* __restrict__ out,         // (B, H, W, D, 3)
    int H, int W)
{
    __shared__ float sm[32][SM_PITCH];      // logit tile, TRANSPOSED: [pixel][depth]
    __shared__ float red[8][32];
    __shared__ float shiftv[32];
    __shared__ float cam0s[32], cam1s[32], cam2s[32];
    __shared__ float4 stageF4[32 * (ST_PITCH / 4)];   // [pixel][96 floats], pitch 100

    float* stf = (float*)stageF4;

    const int tid = threadIdx.x;
    const int tx = tid & 31;
    const int ty = tid >> 5;
    const int tilesPerRow = W >> 5;

    int bid = blockIdx.x;
    int w0 = (bid % tilesPerRow) << 5;
    int h  = (bid / tilesPerRow) % H;
    int b  =  bid / (tilesPerRow * H);

    const size_t HW = (size_t)H * W;
    const float* base = dl + ((size_t)b * D_DEPTH) * HW + (size_t)h * W + w0;

    // Phase 1: coalesced load of 128 x 32 logit tile (store transposed)
    #pragma unroll
    for (int j = 0; j < 16; j++) {
        int d = ty + j * 8;
        sm[tx][d] = base[(size_t)d * HW + tx];   // banks tx+d : conflict-free
    }
    if (ty == 0) {
        const float* k = invK + (size_t)b * 16;
        float x = (float)(w0 + tx), y = (float)h;
        cam0s[tx] = k[0] * x + k[1] * y + k[2];
        cam1s[tx] = k[4] * x + k[5] * y + k[6];
        cam2s[tx] = k[8] * x + k[9] * y + k[10];
    }
    __syncthreads();

    // Phase 2a: per-pixel max over D
    float m = -INFINITY;
    #pragma unroll
    for (int j = 0; j < 16; j++) m = fmaxf(m, sm[tx][ty + j * 8]);
    red[ty][tx] = m;
    __syncthreads();
    if (ty == 0) {
        float mm = red[0][tx];
        #pragma unroll
        for (int r = 1; r < 8; r++) mm = fmaxf(mm, red[r][tx]);
        shiftv[tx] = mm;
    }
    __syncthreads();
    float mpx = shiftv[tx];

    // Phase 2b: per-pixel sum(exp(x-max))
    float s = 0.0f;
    #pragma unroll
    for (int j = 0; j < 16; j++) s += __expf(sm[tx][ty + j * 8] - mpx);
    red[ty][tx] = s;
    __syncthreads();
    if (ty == 0) {
        float ss = 0.0f;
        #pragma unroll
        for (int r = 0; r < 8; r++) ss += red[r][tx];
        shiftv[tx] = -mpx - __logf(ss);   // log_softmax shift
    }
    __syncthreads();

    // Register-cache per-pixel constants (thread's pixel in 3a is always tx)
    const float ca0 = cam0s[tx], ca1 = cam1s[tx], ca2 = cam2s[tx];
    const float sh  = shiftv[tx];

    float* outp = out + (((size_t)b * H + h) * W + w0) * (size_t)(D_DEPTH * 3);
    float4* og4 = (float4*)outp;
    const float4* t4 = &g_logcp4[(size_t)b * CELL];

    // Phase 3: 4 chunks of 32 depths
    for (int c = 0; c < 4; c++) {
        // -- 3a: lane = pixel (tx); this thread: depths 32c + 4ty .. +3
        float vals[12];
        #pragma unroll
        for (int kk = 0; kk < 4; kk++) {
            int d = (c << 5) + (ty << 2) + kk;
            float dlp  = sm[tx][d] + sh;
            float dval = MIN_DEPTH_F + (float)d * RES_F;
            float X =  dval * ca0;
            float Y = -dval * ca1;
            float Z = -dval * ca2;
            int vx = (int)((X - X_MIN_F) / RES_F);   // trunc == astype(int32)
            int vz = (int)((Z + Z_MAX_F) / RES_F);
            float qy = Y / RES_F;                    // trunc(qy)<=0 <=> qy<1
            bool valid = ((unsigned)vx < (unsigned)BEV) &
                         ((unsigned)vz < (unsigned)BEV) & (qy < 1.0f);
            float4 t = make_float4(LOG_U3, LOG_U3, LOG_U3, 0.0f);
            if (valid) t = __ldg(&t4[vz * BEV + vx]);   // warp-uniform vz: 2-3 lines
            vals[kk * 3 + 0] = t.x + dlp;
            vals[kk * 3 + 1] = t.y + dlp;
            vals[kk * 3 + 2] = t.z + dlp;
        }
        // stage[tx][12*ty .. +11] as 3x STS.128 (float4 idx 25*tx + 3*ty + w)
        #pragma unroll
        for (int w = 0; w < 3; w++) {
            stageF4[(ST_PITCH / 4) * tx + 3 * ty + w] =
                make_float4(vals[4 * w + 0], vals[4 * w + 1],
                            vals[4 * w + 2], vals[4 * w + 3]);
        }
        __syncthreads();

        // -- 3b: coalesced copy stage -> gmem. 768 float4 per chunk.
        #pragma unroll
        for (int t = 0; t < 3; t++) {
            int g  = tid + (t << 8);
            int px = g / 24;                 // 24 float4 per pixel per chunk
            int j4 = g - 24 * px;
            float4 v = stageF4[(ST_PITCH / 4) * px + j4];
            __stcs(&og4[(size_t)px * 96 + c * 24 + j4], v);
        }
        __syncthreads();
    }
    (void)stf;
}

// ---------------------------------------------------------------------------
extern "C" void kernel_launch(void* const* d_in, const int* in_sizes, int n_in,
                              void* d_out, int out_size) {
    const float* depth = (const float*)d_in[0];   // depth_logits (B,128,H,W)
    const float* bev   = (const float*)d_in[1];   // bev_logits   (B,2,128,128)
    const float* invK  = (const float*)d_in[2];   // inv_K        (B,4,4)
    float* out = (float*)d_out;

    int B = in_sizes[2] / 16;
    long long HW = (long long)in_sizes[0] / ((long long)B * D_DEPTH);
    int W = 1;
    while ((long long)W * W < HW) W <<= 1;        // square, power-of-two dims
    int H = (int)(HW / W);

    bev_table_kernel<<<(B * CELL + 255) / 256, 256>>>(bev, B);
    decode_kernel<<<B * H * (W / 32), 256>>>(depth, invK, out, H, W);
}

// round 6
// speedup vs baseline: 1.5067x; 1.0877x over previous
#include <cuda_runtime.h>
#include <math.h>

#define D_DEPTH 128
#define BEV 128
#define CELL (BEV*BEV)
#define RES_F 0.025f
#define X_MIN_F (-1.6f)
#define Z_MAX_F 3.3f
#define MIN_DEPTH_F (0.1f + 0.0125f)   /* Z_MIN + RES/2 */
#define LOG_U3 (-1.0986f)
#define EPSC 1e-7f

#define ST_PITCH4 25      /* float4 pitch: 25*16B=400B = 4 mod 32 banks -> conflict-free */

// Interleaved class table: per BEV cell a float4 {logc0, logc1, logc2, 0}.
__device__ float4 g_logcp4[4 * CELL];

// ---------------------------------------------------------------------------
// Kernel 1: bev_logits (B,2,128,128) -> interleaved log class probs
// ---------------------------------------------------------------------------
__global__ void bev_table_kernel(const float* __restrict__ bev, int B) {
    int idx = blockIdx.x * blockDim.x + threadIdx.x;
    if (idx >= B * CELL) return;
    int b = idx / CELL, zx = idx - b * CELL;
    float l0 = bev[(b * 2 + 0) * CELL + zx];
    float l1 = bev[(b * 2 + 1) * CELL + zx];
    float p0 = 1.0f / (1.0f + __expf(-l0));
    float p1 = 1.0f / (1.0f + __expf(-l1));
    p0 = fminf(fmaxf(p0, EPSC), 1.0f - EPSC);
    p1 = fminf(fmaxf(p1, EPSC), 1.0f - EPSC);
    g_logcp4[b * CELL + zx] = make_float4(
        __logf(1.0f - p1), __logf(p1 * p0), __logf(p1 * (1.0f - p0)), 0.0f);
}

// ---------------------------------------------------------------------------
// Kernel 2: block = 32 pixels x 128 depths, 256 threads (32 lanes x 8 warps).
// Thread (tx,ty) owns pixel tx, depths {32c + 4ty + kk : c,kk in 0..3},
// held in 16 REGISTERS end-to-end (no logit smem tile).
// Phase 3a: lane=pixel -> warp-uniform vz gather (2-4 lines/instr).
// Phase 3b: staged transpose -> wavefront-exact coalesced STG.128.
// ---------------------------------------------------------------------------
__global__ __launch_bounds__(256, 6) void decode_kernel(
    const float* __restrict__ dl,    // (B, D, H, W)
    const float* __restrict__ invK,  // (B, 4, 4)
    float* __restrict__ out,         // (B, H, W, D, 3)
    int H, int W)
{
    __shared__ float red[8][32];
    __shared__ float shiftv[32];
    __shared__ float cam0s[32], cam1s[32], cam2s[32];
    __shared__ float4 stageF4[32 * ST_PITCH4];   // 12.8 KB staging

    const int tid = threadIdx.x;
    const int tx = tid & 31;
    const int ty = tid >> 5;
    const int tilesPerRow = W >> 5;

    int bid = blockIdx.x;
    int w0 = (bid % tilesPerRow) << 5;
    int h  = (bid / tilesPerRow) % H;
    int b  =  bid / (tilesPerRow * H);

    const size_t HW = (size_t)H * W;
    const float* base = dl + ((size_t)b * D_DEPTH) * HW + (size_t)h * W + w0
                           + (size_t)(ty << 2) * HW;

    // Phase 1: 16 coalesced LDGs straight into registers.
    // lg[c*4+kk] = logit(pixel tx, depth 32c + 4ty + kk)
    float lg[16];
    #pragma unroll
    for (int c = 0; c < 4; c++)
        #pragma unroll
        for (int kk = 0; kk < 4; kk++)
            lg[c * 4 + kk] = base[(size_t)((c << 5) + kk) * HW + tx];

    if (ty == 0) {
        const float* k = invK + (size_t)b * 16;
        float x = (float)(w0 + tx), y = (float)h;
        cam0s[tx] = k[0] * x + k[1] * y + k[2];
        cam1s[tx] = k[4] * x + k[5] * y + k[6];
        cam2s[tx] = k[8] * x + k[9] * y + k[10];
    }

    // Phase 2a: per-pixel max over D (register partials + cross-warp combine)
    float m = lg[0];
    #pragma unroll
    for (int j = 1; j < 16; j++) m = fmaxf(m, lg[j]);
    red[ty][tx] = m;
    __syncthreads();
    if (ty == 0) {
        float mm = red[0][tx];
        #pragma unroll
        for (int r = 1; r < 8; r++) mm = fmaxf(mm, red[r][tx]);
        shiftv[tx] = mm;
    }
    __syncthreads();
    float mpx = shiftv[tx];

    // Phase 2b: per-pixel sum(exp(x-max))
    float s = 0.0f;
    #pragma unroll
    for (int j = 0; j < 16; j++) s += __expf(lg[j] - mpx);
    red[ty][tx] = s;
    __syncthreads();
    if (ty == 0) {
        float ss = 0.0f;
        #pragma unroll
        for (int r = 0; r < 8; r++) ss += red[r][tx];
        shiftv[tx] = -mpx - __logf(ss);   // log_softmax shift
    }
    __syncthreads();

    const float ca0 = cam0s[tx], ca1 = cam1s[tx], ca2 = cam2s[tx];
    const float sh  = shiftv[tx];

    float* outp = out + (((size_t)b * H + h) * W + w0) * (size_t)(D_DEPTH * 3);
    float4* og4 = (float4*)outp;
    const float4* t4 = &g_logcp4[(size_t)b * CELL];

    // Phase 3: 4 chunks of 32 depths (fully unrolled: lg indices static)
    #pragma unroll
    for (int c = 0; c < 4; c++) {
        float vals[12];
        #pragma unroll
        for (int kk = 0; kk < 4; kk++) {
            int d = (c << 5) + (ty << 2) + kk;
            float dlp  = lg[c * 4 + kk] + sh;
            float dval = MIN_DEPTH_F + (float)d * RES_F;
            float X =  dval * ca0;
            float Y = -dval * ca1;
            float Z = -dval * ca2;
            int vx = (int)((X - X_MIN_F) / RES_F);   // trunc == astype(int32)
            int vz = (int)((Z + Z_MAX_F) / RES_F);
            float qy = Y / RES_F;                    // trunc(qy)<=0 <=> qy<1
            bool valid = ((unsigned)vx < (unsigned)BEV) &
                         ((unsigned)vz < (unsigned)BEV) & (qy < 1.0f);
            float4 t = make_float4(LOG_U3, LOG_U3, LOG_U3, 0.0f);
            if (valid) t = __ldg(&t4[vz * BEV + vx]);   // warp-uniform vz
            vals[kk * 3 + 0] = t.x + dlp;
            vals[kk * 3 + 1] = t.y + dlp;
            vals[kk * 3 + 2] = t.z + dlp;
        }
        // stage[pixel tx][12 floats at 12*ty] as 3x STS.128 (conflict-free)
        #pragma unroll
        for (int w = 0; w < 3; w++) {
            stageF4[ST_PITCH4 * tx + 3 * ty + w] =
                make_float4(vals[4 * w + 0], vals[4 * w + 1],
                            vals[4 * w + 2], vals[4 * w + 3]);
        }
        __syncthreads();

        // Phase 3b: coalesced copy stage -> gmem. 768 float4 per chunk.
        #pragma unroll
        for (int t = 0; t < 3; t++) {
            int g  = tid + (t << 8);
            int px = g / 24;                 // 24 float4 per pixel per chunk
            int j4 = g - 24 * px;
            float4 v = stageF4[ST_PITCH4 * px + j4];
            __stcs(&og4[(size_t)px * 96 + c * 24 + j4], v);
        }
        __syncthreads();
    }
}

// ---------------------------------------------------------------------------
extern "C" void kernel_launch(void* const* d_in, const int* in_sizes, int n_in,
                              void* d_out, int out_size) {
    const float* depth = (const float*)d_in[0];   // depth_logits (B,128,H,W)
    const float* bev   = (const float*)d_in[1];   // bev_logits   (B,2,128,128)
    const float* invK  = (const float*)d_in[2];   // inv_K        (B,4,4)
    float* out = (float*)d_out;

    int B = in_sizes[2] / 16;
    long long HW = (long long)in_sizes[0] / ((long long)B * D_DEPTH);
    int W = 1;
    while ((long long)W * W < HW) W <<= 1;        // square, power-of-two dims
    int H = (int)(HW / W);

    bev_table_kernel<<<(B * CELL + 255) / 256, 256>>>(bev, B);
    decode_kernel<<<B * H * (W / 32), 256>>>(depth, invK, out, H, W);
}

// round 7
// speedup vs baseline: 1.7698x; 1.1747x over previous
#include <cuda_runtime.h>
#include <math.h>

#define D_DEPTH 128
#define BEV 128
#define CELL (BEV*BEV)
#define RES_F 0.025f
#define LOG_U3 (-1.0986f)
#define EPSC 1e-7f

#define ST_PITCH4 25      /* float4 pitch: 100 words = 4 mod 32 banks */

// Interleaved class table: per BEV cell a float4 {logc0, logc1, logc2, 0}.
__device__ float4 g_logcp4[4 * CELL];

// ---------------------------------------------------------------------------
// Kernel 1: bev_logits (B,2,128,128) -> interleaved log class probs
// ---------------------------------------------------------------------------
__global__ void bev_table_kernel(const float* __restrict__ bev, int B) {
    int idx = blockIdx.x * blockDim.x + threadIdx.x;
    if (idx >= B * CELL) return;
    int b = idx / CELL, zx = idx - b * CELL;
    float l0 = bev[(b * 2 + 0) * CELL + zx];
    float l1 = bev[(b * 2 + 1) * CELL + zx];
    float p0 = 1.0f / (1.0f + __expf(-l0));
    float p1 = 1.0f / (1.0f + __expf(-l1));
    p0 = fminf(fmaxf(p0, EPSC), 1.0f - EPSC);
    p1 = fminf(fmaxf(p1, EPSC), 1.0f - EPSC);
    g_logcp4[b * CELL + zx] = make_float4(
        __logf(1.0f - p1), __logf(p1 * p0), __logf(p1 * (1.0f - p0)), 0.0f);
}

// ---------------------------------------------------------------------------
// Kernel 2: block = 32 pixels x 128 depths, 256 threads (32 lanes x 8 warps).
// Thread (tx,ty): pixel tx, depths {32c + 4ty + kk}. Logits in registers.
// Voxel math: u = d+4.5 exact; vx=fma(u,ca0,64), vz=fma(-u,ca2,132) -- no FDIV.
// Double-buffered staging: 4 syncthreads total.
// ---------------------------------------------------------------------------
__global__ __launch_bounds__(256, 6) void decode_kernel(
    const float* __restrict__ dl,    // (B, D, H, W)
    const float* __restrict__ invK,  // (B, 4, 4)
    float* __restrict__ out,         // (B, H, W, D, 3)
    int H, int W)
{
    __shared__ float red[8][32];
    __shared__ float shiftv[32];
    __shared__ float cam0s[32], cam1s[32], cam2s[32];
    __shared__ float4 stageF4[2][32 * ST_PITCH4];   // double buffer, 2 x 12.8 KB

    const int tid = threadIdx.x;
    const int tx = tid & 31;
    const int ty = tid >> 5;
    const int tilesPerRow = W >> 5;

    int bid = blockIdx.x;
    int w0 = (bid % tilesPerRow) << 5;
    int h  = (bid / tilesPerRow) % H;
    int b  =  bid / (tilesPerRow * H);

    const size_t HW = (size_t)H * W;
    const float* bp = dl + ((size_t)b * D_DEPTH + (size_t)(ty << 2)) * HW
                        + (size_t)h * W + w0 + tx;

    // Phase 1: 16 coalesced LDGs straight into registers.
    float lg[16];
    #pragma unroll
    for (int c = 0; c < 4; c++)
        #pragma unroll
        for (int kk = 0; kk < 4; kk++)
            lg[c * 4 + kk] = __ldg(&bp[(size_t)((c << 5) + kk) * HW]);

    if (ty == 0) {
        const float* k = invK + (size_t)b * 16;
        float x = (float)(w0 + tx), y = (float)h;
        cam0s[tx] = k[0] * x + k[1] * y + k[2];
        cam1s[tx] = k[4] * x + k[5] * y + k[6];
        cam2s[tx] = k[8] * x + k[9] * y + k[10];
    }

    // Phase 2a: per-pixel max over D
    float m = lg[0];
    #pragma unroll
    for (int j = 1; j < 16; j++) m = fmaxf(m, lg[j]);
    red[ty][tx] = m;
    __syncthreads();
    if (ty == 0) {
        float mm = red[0][tx];
        #pragma unroll
        for (int r = 1; r < 8; r++) mm = fmaxf(mm, red[r][tx]);
        shiftv[tx] = mm;
    }
    __syncthreads();
    float mpx = shiftv[tx];

    // Phase 2b: per-pixel sum(exp(x-max))
    float s = 0.0f;
    #pragma unroll
    for (int j = 0; j < 16; j++) s += __expf(lg[j] - mpx);
    red[ty][tx] = s;
    __syncthreads();
    if (ty == 0) {
        float ss = 0.0f;
        #pragma unroll
        for (int r = 0; r < 8; r++) ss += red[r][tx];
        shiftv[tx] = -mpx - __logf(ss);   // log_softmax shift
    }
    __syncthreads();

    const float ca0 = cam0s[tx], ca1 = cam1s[tx], ca2 = cam2s[tx];
    const float sh  = shiftv[tx];

    float* outp = out + (((size_t)b * H + h) * W + w0) * (size_t)(D_DEPTH * 3);
    float4* og4 = (float4*)outp;
    const float4* t4 = &g_logcp4[(size_t)b * CELL];

    const int px_o = tid >> 3;          // 3b pixel (shift-only mapping)
    const int tq   = tid & 7;

    // Phase 3: 4 chunks of 32 depths, double-buffered staging
    #pragma unroll
    for (int c = 0; c < 4; c++) {
        float4* stg = stageF4[c & 1];
        const float ub = 4.5f + (float)((c << 5) + (ty << 2));  // u = d + 4.5 (exact)

        float vals[12];
        #pragma unroll
        for (int kk = 0; kk < 4; kk++) {
            float u   = ub + (float)kk;
            float dlp = lg[c * 4 + kk] + sh;
            float vxf = fmaf(u,  ca0,  64.0f);   // (X - X_MIN)/RES
            float vzf = fmaf(-u, ca2, 132.0f);   // (Z + Z_MAX)/RES
            float qy  = -u * ca1;                // Y/RES ; trunc<=0 <=> qy<1
            int vx = (int)vxf;
            int vz = (int)vzf;
            bool valid = ((unsigned)vx < (unsigned)BEV) &
                         ((unsigned)vz < (unsigned)BEV) & (qy < 1.0f);
            float4 t = make_float4(LOG_U3, LOG_U3, LOG_U3, 0.0f);
            if (valid) t = __ldg(&t4[vz * BEV + vx]);   // warp-uniform vz
            vals[kk * 3 + 0] = t.x + dlp;
            vals[kk * 3 + 1] = t.y + dlp;
            vals[kk * 3 + 2] = t.z + dlp;
        }
        #pragma unroll
        for (int w = 0; w < 3; w++) {
            stg[ST_PITCH4 * tx + 3 * ty + w] =
                make_float4(vals[4 * w + 0], vals[4 * w + 1],
                            vals[4 * w + 2], vals[4 * w + 3]);
        }
        __syncthreads();

        // Phase 3b: wavefront-exact copy stage -> gmem (shift-only indexing)
        #pragma unroll
        for (int r = 0; r < 3; r++) {
            int j4 = tq + (r << 3);          // 0..23, 8 contiguous f4 per 8 lanes
            float4 v = stg[ST_PITCH4 * px_o + j4];
            __stcs(&og4[(size_t)px_o * 96 + (c * 24) + j4], v);
        }
        // no second sync: next chunk writes the other buffer
    }
}

// ---------------------------------------------------------------------------
extern "C" void kernel_launch(void* const* d_in, const int* in_sizes, int n_in,
                              void* d_out, int out_size) {
    const float* depth = (const float*)d_in[0];   // depth_logits (B,128,H,W)
    const float* bev   = (const float*)d_in[1];   // bev_logits   (B,2,128,128)
    const float* invK  = (const float*)d_in[2];   // inv_K        (B,4,4)
    float* out = (float*)d_out;

    int B = in_sizes[2] / 16;
    long long HW = (long long)in_sizes[0] / ((long long)B * D_DEPTH);
    int W = 1;
    while ((long long)W * W < HW) W <<= 1;        // square, power-of-two dims
    int H = (int)(HW / W);

    bev_table_kernel<<<(B * CELL + 255) / 256, 256>>>(bev, B);
    decode_kernel<<<B * H * (W / 32), 256>>>(depth, invK, out, H, W);
}